// round 3
// baseline (speedup 1.0000x reference)
#include <cuda_runtime.h>

#define N0 8000
#define N1 4000
#define N2 2000
#define DIM 128
#define XW 384  // 3*DIM

// Scratch (module-load allocated, zero-initialized — legal under _HX_ENFORCE)
__device__ float g_X0[N0 * XW];
__device__ float g_X1[N1 * XW];
__device__ float g_X2[N2 * XW];
__device__ float g_Y0[N0 * XW];
__device__ float g_Y1[N1 * XW];
__device__ float g_Y2[N2 * XW];

// ---------------------------------------------------------------------------
// Zero a float buffer (n divisible by 4)
// ---------------------------------------------------------------------------
__global__ void k_zero(float* __restrict__ p, int n4) {
    int i = blockIdx.x * blockDim.x + threadIdx.x;
    int stride = gridDim.x * blockDim.x;
    float4 z = make_float4(0.f, 0.f, 0.f, 0.f);
    for (; i < n4; i += stride)
        reinterpret_cast<float4*>(p)[i] = z;
}

// ---------------------------------------------------------------------------
// Place a (rows x 128) block of H into X at column offset col_off.
//   dst row = d1[d2[r]] (chain, optional), src row = s1[s2[r]] (chain, optional)
// 128 threads/block, 4 rows per block, float4 per thread.
// ---------------------------------------------------------------------------
__global__ void k_place(float* __restrict__ X, const float* __restrict__ H,
                        int rows,
                        const int* __restrict__ d1, const int* __restrict__ d2,
                        const int* __restrict__ s1, const int* __restrict__ s2,
                        int col_off) {
    int r = blockIdx.x * 4 + (threadIdx.x >> 5);
    int c4 = threadIdx.x & 31;
    if (r >= rows) return;
    int sr = r;
    if (s2) sr = s2[sr];
    if (s1) sr = s1[sr];
    int dr = r;
    if (d2) dr = d2[dr];
    if (d1) dr = d1[dr];
    reinterpret_cast<float4*>(X + (size_t)dr * XW + col_off)[c4] =
        reinterpret_cast<const float4*>(H + (size_t)sr * DIM)[c4];
}

// ---------------------------------------------------------------------------
// SGEMM: C[M x 384] = A[M x K] * B[K x 384]
// 128x128 tile, BK=16, 256 threads, 8x8 per thread. K divisible by 16.
// ---------------------------------------------------------------------------
__global__ __launch_bounds__(256) void k_sgemm(const float* __restrict__ A,
                                               const float* __restrict__ B,
                                               float* __restrict__ C,
                                               int M, int K) {
    __shared__ float As[16][132];  // transposed [k][m], pad keeps 16B align (132%4==0)
    __shared__ float Bs[16][128];

    int tid = threadIdx.x;
    int tx = tid & 15;        // col thread 0..15
    int ty = tid >> 4;        // row thread 0..15
    int rowBase = blockIdx.y * 128;
    int colBase = blockIdx.x * 128;

    float acc[8][8];
#pragma unroll
    for (int i = 0; i < 8; i++)
#pragma unroll
        for (int j = 0; j < 8; j++) acc[i][j] = 0.f;

    for (int k0 = 0; k0 < K; k0 += 16) {
        // Load A tile (128 rows x 16 k), transpose into As[k][row]
#pragma unroll
        for (int l = 0; l < 2; l++) {
            int s = tid + l * 256;        // 0..511
            int r = s >> 2;               // 0..127
            int kq = (s & 3) * 4;         // 0,4,8,12
            int grow = rowBase + r;
            float4 v = make_float4(0.f, 0.f, 0.f, 0.f);
            if (grow < M)
                v = *reinterpret_cast<const float4*>(A + (size_t)grow * K + k0 + kq);
            As[kq + 0][r] = v.x;
            As[kq + 1][r] = v.y;
            As[kq + 2][r] = v.z;
            As[kq + 3][r] = v.w;
        }
        // Load B tile (16 k x 128 cols)
#pragma unroll
        for (int l = 0; l < 2; l++) {
            int s = tid + l * 256;
            int kr = s >> 5;              // 0..15
            int c4 = (s & 31) * 4;        // 0..124
            *reinterpret_cast<float4*>(&Bs[kr][c4]) =
                *reinterpret_cast<const float4*>(B + (size_t)(k0 + kr) * XW + colBase + c4);
        }
        __syncthreads();

#pragma unroll
        for (int kk = 0; kk < 16; kk++) {
            float a[8], b[8];
            *reinterpret_cast<float4*>(a) = *reinterpret_cast<const float4*>(&As[kk][ty * 8]);
            *reinterpret_cast<float4*>(a + 4) = *reinterpret_cast<const float4*>(&As[kk][ty * 8 + 4]);
            *reinterpret_cast<float4*>(b) = *reinterpret_cast<const float4*>(&Bs[kk][tx * 8]);
            *reinterpret_cast<float4*>(b + 4) = *reinterpret_cast<const float4*>(&Bs[kk][tx * 8 + 4]);
#pragma unroll
            for (int i = 0; i < 8; i++)
#pragma unroll
                for (int j = 0; j < 8; j++) acc[i][j] += a[i] * b[j];
        }
        __syncthreads();
    }

#pragma unroll
    for (int i = 0; i < 8; i++) {
        int grow = rowBase + ty * 8 + i;
        if (grow < M) {
            float* cp = C + (size_t)grow * XW + colBase + tx * 8;
            *reinterpret_cast<float4*>(cp) =
                make_float4(acc[i][0], acc[i][1], acc[i][2], acc[i][3]);
            *reinterpret_cast<float4*>(cp + 4) =
                make_float4(acc[i][4], acc[i][5], acc[i][6], acc[i][7]);
        }
    }
}

// ---------------------------------------------------------------------------
// Epilogue: out[M x 128] = sum_j relu( Y[:, j*128:(j+1)*128] @ W[ilev][j] + b[ilev][j] )
// 128x128 tile per block, K=128 per j.
// ---------------------------------------------------------------------------
__global__ __launch_bounds__(256) void k_epi(const float* __restrict__ Y,
                                             const float* __restrict__ Wall,
                                             const float* __restrict__ ball,
                                             float* __restrict__ out,
                                             int M, int ilev) {
    __shared__ float As[16][132];
    __shared__ float Bs[16][128];

    int tid = threadIdx.x;
    int tx = tid & 15;
    int ty = tid >> 4;
    int rowBase = blockIdx.x * 128;

    float sum[8][8];
#pragma unroll
    for (int i = 0; i < 8; i++)
#pragma unroll
        for (int j = 0; j < 8; j++) sum[i][j] = 0.f;

    for (int jb = 0; jb < 3; jb++) {
        const float* W = Wall + (size_t)(ilev * 3 + jb) * DIM * DIM;
        float acc[8][8];
#pragma unroll
        for (int i = 0; i < 8; i++)
#pragma unroll
            for (int j = 0; j < 8; j++) acc[i][j] = 0.f;

        for (int k0 = 0; k0 < DIM; k0 += 16) {
#pragma unroll
            for (int l = 0; l < 2; l++) {
                int s = tid + l * 256;
                int r = s >> 2;
                int kq = (s & 3) * 4;
                int grow = rowBase + r;
                float4 v = make_float4(0.f, 0.f, 0.f, 0.f);
                if (grow < M)
                    v = *reinterpret_cast<const float4*>(
                        Y + (size_t)grow * XW + jb * DIM + k0 + kq);
                As[kq + 0][r] = v.x;
                As[kq + 1][r] = v.y;
                As[kq + 2][r] = v.z;
                As[kq + 3][r] = v.w;
            }
#pragma unroll
            for (int l = 0; l < 2; l++) {
                int s = tid + l * 256;
                int kr = s >> 5;
                int c4 = (s & 31) * 4;
                *reinterpret_cast<float4*>(&Bs[kr][c4]) =
                    *reinterpret_cast<const float4*>(W + (size_t)(k0 + kr) * DIM + c4);
            }
            __syncthreads();
#pragma unroll
            for (int kk = 0; kk < 16; kk++) {
                float a[8], b[8];
                *reinterpret_cast<float4*>(a) = *reinterpret_cast<const float4*>(&As[kk][ty * 8]);
                *reinterpret_cast<float4*>(a + 4) = *reinterpret_cast<const float4*>(&As[kk][ty * 8 + 4]);
                *reinterpret_cast<float4*>(b) = *reinterpret_cast<const float4*>(&Bs[kk][tx * 8]);
                *reinterpret_cast<float4*>(b + 4) = *reinterpret_cast<const float4*>(&Bs[kk][tx * 8 + 4]);
#pragma unroll
                for (int i = 0; i < 8; i++)
#pragma unroll
                    for (int j = 0; j < 8; j++) acc[i][j] += a[i] * b[j];
            }
            __syncthreads();
        }
        const float* bvec = ball + (size_t)(ilev * 3 + jb) * DIM;
#pragma unroll
        for (int j = 0; j < 8; j++) {
            float bb = bvec[tx * 8 + j];
#pragma unroll
            for (int i = 0; i < 8; i++) sum[i][j] += fmaxf(acc[i][j] + bb, 0.f);
        }
    }

#pragma unroll
    for (int i = 0; i < 8; i++) {
        int grow = rowBase + ty * 8 + i;
        if (grow < M) {
            float* op = out + (size_t)grow * DIM + tx * 8;
            *reinterpret_cast<float4*>(op) =
                make_float4(sum[i][0], sum[i][1], sum[i][2], sum[i][3]);
            *reinterpret_cast<float4*>(op + 4) =
                make_float4(sum[i][4], sum[i][5], sum[i][6], sum[i][7]);
        }
    }
}

// ---------------------------------------------------------------------------
extern "C" void kernel_launch(void* const* d_in, const int* in_sizes, int n_in,
                              void* d_out, int out_size) {
    const float* adj0 = (const float*)d_in[0];
    const float* adj1 = (const float*)d_in[1];
    const float* adj2 = (const float*)d_in[2];
    const float* h0 = (const float*)d_in[3];
    const float* h1 = (const float*)d_in[4];
    const float* h2 = (const float*)d_in[5];
    const int* idx0 = (const int*)d_in[6];
    const int* idx1 = (const int*)d_in[7];
    const float* Ws = (const float*)d_in[8];
    const float* bs = (const float*)d_in[9];
    float* out = (float*)d_out;

    float *X0, *X1, *X2, *Y0, *Y1, *Y2;
    cudaGetSymbolAddress((void**)&X0, g_X0);
    cudaGetSymbolAddress((void**)&X1, g_X1);
    cudaGetSymbolAddress((void**)&X2, g_X2);
    cudaGetSymbolAddress((void**)&Y0, g_Y0);
    cudaGetSymbolAddress((void**)&Y1, g_Y1);
    cudaGetSymbolAddress((void**)&Y2, g_Y2);

    // 1. Zero X (scatter blocks need zeros; zero everything — cheap)
    k_zero<<<512, 256>>>(X0, N0 * XW / 4);
    k_zero<<<512, 256>>>(X1, N1 * XW / 4);
    k_zero<<<512, 256>>>(X2, N2 * XW / 4);

    // 2. Build X_i = [xfm(h0) | xfm(h1) | xfm(h2)] at each level
    // Level 0 (targets N0 rows):
    k_place<<<N0 / 4, 128>>>(X0, h0, N0, nullptr, nullptr, nullptr, nullptr, 0);
    k_place<<<N1 / 4, 128>>>(X0, h1, N1, idx0, nullptr, nullptr, nullptr, 128);     // scatter via idx0
    k_place<<<N2 / 4, 128>>>(X0, h2, N2, idx0, idx1, nullptr, nullptr, 256);        // scatter via idx0[idx1]
    // Level 1:
    k_place<<<N1 / 4, 128>>>(X1, h0, N1, nullptr, nullptr, idx0, nullptr, 0);       // gather idx0
    k_place<<<N1 / 4, 128>>>(X1, h1, N1, nullptr, nullptr, nullptr, nullptr, 128);
    k_place<<<N2 / 4, 128>>>(X1, h2, N2, idx1, nullptr, nullptr, nullptr, 256);     // scatter via idx1
    // Level 2:
    k_place<<<N2 / 4, 128>>>(X2, h0, N2, nullptr, nullptr, idx0, idx1, 0);          // gather idx0[idx1]
    k_place<<<N2 / 4, 128>>>(X2, h1, N2, nullptr, nullptr, idx1, nullptr, 128);     // gather idx1
    k_place<<<N2 / 4, 128>>>(X2, h2, N2, nullptr, nullptr, nullptr, nullptr, 256);

    // 3. Y_i = adj_i @ X_i  (the heavy GEMMs)
    {
        dim3 g0(3, (N0 + 127) / 128);
        k_sgemm<<<g0, 256>>>(adj0, X0, Y0, N0, N0);
        dim3 g1(3, (N1 + 127) / 128);
        k_sgemm<<<g1, 256>>>(adj1, X1, Y1, N1, N1);
        dim3 g2(3, (N2 + 127) / 128);
        k_sgemm<<<g2, 256>>>(adj2, X2, Y2, N2, N2);
    }

    // 4. out_i = sum_j relu(Y_i[:,jblk] @ W[i,j] + b[i,j])
    k_epi<<<(N0 + 127) / 128, 256>>>(Y0, Ws, bs, out, N0, 0);
    k_epi<<<(N1 + 127) / 128, 256>>>(Y1, Ws, bs, out + (size_t)N0 * DIM, N1, 1);
    k_epi<<<(N2 + 127) / 128, 256>>>(Y2, Ws, bs, out + (size_t)(N0 + N1) * DIM, N2, 2);
}

// round 5
// speedup vs baseline: 3.0825x; 3.0825x over previous
#include <cuda_runtime.h>
#include <cuda_bf16.h>
#include <cstdint>

#define N0 8000
#define N1 4000
#define N2 2000
#define DIM 128
#define XW 384

// Scratch: Xt_i = X^T, layout [384][N_i] (row = feature, K-contiguous). Y = [N_i][384].
__device__ float g_X0[N0 * XW];
__device__ float g_X1[N1 * XW];
__device__ float g_X2[N2 * XW];
__device__ float g_Y0[N0 * XW];
__device__ float g_Y1[N1 * XW];
__device__ float g_Y2[N2 * XW];

// Smem tile geometry: 128 rows x 32 bf16, rows padded to 80B (conflict-free ldmatrix)
#define ROWB 80
#define TILE_BYTES (128 * ROWB)      // 10240
#define BUF_BYTES (4 * TILE_BYTES)   // Ahi|Alo|Bhi|Blo = 40960
#define SMEM_TOTAL (2 * BUF_BYTES)   // 81920 (double buffered)

// ===========================================================================
// helpers
// ===========================================================================
__device__ __forceinline__ uint32_t smem_to_u32(const void* p) {
    uint32_t a;
    asm("{ .reg .u64 t; cvta.to.shared.u64 t, %1; cvt.u32.u64 %0, t; }" : "=r"(a) : "l"(p));
    return a;
}

__device__ __forceinline__ void ldsm4(uint32_t* r, uint32_t addr) {
    asm volatile("ldmatrix.sync.aligned.m8n8.x4.shared.b16 {%0,%1,%2,%3}, [%4];"
                 : "=r"(r[0]), "=r"(r[1]), "=r"(r[2]), "=r"(r[3]) : "r"(addr));
}

__device__ __forceinline__ void mma16816(float* c, const uint32_t* a, const uint32_t* b) {
    asm volatile(
        "mma.sync.aligned.m16n8k16.row.col.f32.bf16.bf16.f32 "
        "{%0,%1,%2,%3}, {%4,%5,%6,%7}, {%8,%9}, {%0,%1,%2,%3};"
        : "+f"(c[0]), "+f"(c[1]), "+f"(c[2]), "+f"(c[3])
        : "r"(a[0]), "r"(a[1]), "r"(a[2]), "r"(a[3]), "r"(b[0]), "r"(b[1]));
}

__device__ __forceinline__ uint32_t pkbits(__nv_bfloat16 x, __nv_bfloat16 y) {
    __nv_bfloat162 t;
    t.x = x; t.y = y;
    return reinterpret_cast<uint32_t&>(t);
}

// 8 fp32 -> 16B bf16 hi + 16B bf16 lo (residual), stored to smem
__device__ __forceinline__ void cvt8(char* hiP, char* loP, float4 a, float4 b) {
    float f[8] = {a.x, a.y, a.z, a.w, b.x, b.y, b.z, b.w};
    uint32_t hi[4], lo[4];
#pragma unroll
    for (int i = 0; i < 4; i++) {
        __nv_bfloat16 x = __float2bfloat16_rn(f[2 * i]);
        __nv_bfloat16 y = __float2bfloat16_rn(f[2 * i + 1]);
        hi[i] = pkbits(x, y);
        float rx = f[2 * i] - __bfloat162float(x);
        float ry = f[2 * i + 1] - __bfloat162float(y);
        lo[i] = pkbits(__float2bfloat16_rn(rx), __float2bfloat16_rn(ry));
    }
    *reinterpret_cast<uint4*>(hiP) = make_uint4(hi[0], hi[1], hi[2], hi[3]);
    *reinterpret_cast<uint4*>(loP) = make_uint4(lo[0], lo[1], lo[2], lo[3]);
}

__device__ __forceinline__ void load_tiles(float4* va, float4* vb,
                                           const float* __restrict__ A,
                                           const float* __restrict__ B,
                                           int M, int K, int rowBase, int nBase,
                                           int k0, int tid) {
#pragma unroll
    for (int t = 0; t < 2; t++) {
        int idx = tid + t * 256;
        int row = idx >> 2;
        int q = idx & 3;
        int gk = k0 + q * 8;
        int gr = rowBase + row;
        if (gr < M && gk < K) {
            const float* p = A + (size_t)gr * K + gk;
            va[2 * t] = *reinterpret_cast<const float4*>(p);
            va[2 * t + 1] = *reinterpret_cast<const float4*>(p + 4);
        } else {
            va[2 * t] = va[2 * t + 1] = make_float4(0.f, 0.f, 0.f, 0.f);
        }
        if (gk < K) {
            const float* p = B + (size_t)(nBase + row) * K + gk;
            vb[2 * t] = *reinterpret_cast<const float4*>(p);
            vb[2 * t + 1] = *reinterpret_cast<const float4*>(p + 4);
        } else {
            vb[2 * t] = vb[2 * t + 1] = make_float4(0.f, 0.f, 0.f, 0.f);
        }
    }
}

// ===========================================================================
// Utility kernels
// ===========================================================================
__global__ void k_zero(float* __restrict__ p, int n4) {
    int i = blockIdx.x * blockDim.x + threadIdx.x;
    int stride = gridDim.x * blockDim.x;
    float4 z = make_float4(0.f, 0.f, 0.f, 0.f);
    for (; i < n4; i += stride) reinterpret_cast<float4*>(p)[i] = z;
}

// Transposed placement, contiguous dst: Xt[rowOff+f][r] = H[chain(r)][f]
__global__ __launch_bounds__(256) void k_trans(float* __restrict__ Xt, int ld,
                                               const float* __restrict__ H, int rows,
                                               const int* __restrict__ s1,
                                               const int* __restrict__ s2, int rowOff) {
    __shared__ float tile[128][33];
    int tid = threadIdx.x;
    int r0 = blockIdx.x * 32;
#pragma unroll
    for (int t = 0; t < 4; t++) {
        int g = tid + t * 256;
        int r = g >> 5;
        int c4 = g & 31;
        int sr = r0 + r;
        float4 v = make_float4(0.f, 0.f, 0.f, 0.f);
        if (sr < rows) {
            int s = sr;
            if (s2) s = s2[s];
            if (s1) s = s1[s];
            v = *reinterpret_cast<const float4*>(H + (size_t)s * DIM + c4 * 4);
        }
        tile[c4 * 4 + 0][r] = v.x;
        tile[c4 * 4 + 1][r] = v.y;
        tile[c4 * 4 + 2][r] = v.z;
        tile[c4 * 4 + 3][r] = v.w;
    }
    __syncthreads();
    int f = tid >> 1;
    int half = tid & 1;
#pragma unroll
    for (int m4 = 0; m4 < 4; m4++) {
        int lc = half * 16 + m4 * 4;
        int col = r0 + lc;
        if (col < rows) {
            float4 w = make_float4(tile[f][lc], tile[f][lc + 1], tile[f][lc + 2], tile[f][lc + 3]);
            *reinterpret_cast<float4*>(Xt + (size_t)(rowOff + f) * ld + col) = w;
        }
    }
}

// Transposed placement, scattered dst columns (up path)
__global__ void k_scatter(float* __restrict__ Xt, int ld, const float* __restrict__ H,
                          const int* __restrict__ d1, const int* __restrict__ d2, int rowOff) {
    int r = blockIdx.x;
    int f = threadIdx.x;
    float v = H[(size_t)r * DIM + f];
    int dr = r;
    if (d2) dr = d2[dr];
    if (d1) dr = d1[dr];
    Xt[(size_t)(rowOff + f) * ld + dr] = v;
}

// ===========================================================================
// bf16-split mma.sync GEMM: Y[M x 384] = adj[M x K] * Xt^T   (Xt: [384 x K])
// Grid: 333 CTAs (level0: 63 mt x 3 nt, level1: 32x3, level2: 16x3), nt fastest.
// ===========================================================================
__global__ __launch_bounds__(256, 1)
void k_mma(const float* __restrict__ A0, const float* __restrict__ A1, const float* __restrict__ A2,
           const float* __restrict__ B0, const float* __restrict__ B1, const float* __restrict__ B2,
           float* __restrict__ Y0, float* __restrict__ Y1, float* __restrict__ Y2) {
    extern __shared__ char sm[];
    int tid = threadIdx.x;
    int lane = tid & 31;
    int wid = tid >> 5;
    int bx = blockIdx.x;

    const float* A;
    const float* B;
    float* Y;
    int M, mt, nt;
    if (bx < 189) {
        A = A0; B = B0; Y = Y0; M = N0; mt = bx / 3; nt = bx % 3;
    } else if (bx < 285) {
        int r = bx - 189;
        A = A1; B = B1; Y = Y1; M = N1; mt = r / 3; nt = r % 3;
    } else {
        int r = bx - 285;
        A = A2; B = B2; Y = Y2; M = N2; mt = r / 3; nt = r % 3;
    }
    int K = M;
    int rowBase = mt * 128;
    int nBase = nt * 128;
    int nIter = (K + 31) / 32;

    uint32_t sbase = smem_to_u32(sm);
    int wm = wid & 3;    // m warp (0..3) -> 32 rows
    int wn = wid >> 2;   // n warp (0..1) -> 64 cols

    // ldmatrix per-lane offsets (bytes within a tile)
    uint32_t aoff[2], boff[4];
#pragma unroll
    for (int mi = 0; mi < 2; mi++)
        aoff[mi] = (uint32_t)(wm * 32 + mi * 16 + (lane & 15)) * ROWB + (uint32_t)(lane >> 4) * 16;
#pragma unroll
    for (int nb = 0; nb < 4; nb++)
        boff[nb] = (uint32_t)(wn * 64 + nb * 16 + (lane & 7) + ((lane >> 4) & 1) * 8) * ROWB +
                   (uint32_t)((lane >> 3) & 1) * 16;

    float acc[2][8][4];
#pragma unroll
    for (int mi = 0; mi < 2; mi++)
#pragma unroll
        for (int ni = 0; ni < 8; ni++)
#pragma unroll
            for (int c = 0; c < 4; c++) acc[mi][ni][c] = 0.f;

    float4 va[4], vb[4];
    load_tiles(va, vb, A, B, M, K, rowBase, nBase, 0, tid);

    for (int it = 0; it < nIter; it++) {
        char* buf = sm + (size_t)(it & 1) * BUF_BYTES;
        // convert + STS (hi/lo tiles)
#pragma unroll
        for (int t = 0; t < 2; t++) {
            int idx = tid + t * 256;
            int row = idx >> 2;
            int q = idx & 3;
            uint32_t off = (uint32_t)row * ROWB + (uint32_t)q * 16;
            cvt8(buf + off, buf + TILE_BYTES + off, va[2 * t], va[2 * t + 1]);
            cvt8(buf + 2 * TILE_BYTES + off, buf + 3 * TILE_BYTES + off, vb[2 * t], vb[2 * t + 1]);
        }
        if (it + 1 < nIter)
            load_tiles(va, vb, A, B, M, K, rowBase, nBase, (it + 1) * 32, tid);
        __syncthreads();

        uint32_t Ah = sbase + (uint32_t)(it & 1) * BUF_BYTES;
        uint32_t Al = Ah + TILE_BYTES;
        uint32_t Bh = Ah + 2 * TILE_BYTES;
        uint32_t Bl = Ah + 3 * TILE_BYTES;
#pragma unroll
        for (int k16 = 0; k16 < 2; k16++) {
            uint32_t ko = (uint32_t)k16 * 32;
            uint32_t ah[2][4], al[2][4], bh[4][4], bl[4][4];
            ldsm4(ah[0], Ah + aoff[0] + ko);
            ldsm4(ah[1], Ah + aoff[1] + ko);
#pragma unroll
            for (int nb = 0; nb < 4; nb++) ldsm4(bh[nb], Bh + boff[nb] + ko);
            // Ah * Bh
#pragma unroll
            for (int mi = 0; mi < 2; mi++)
#pragma unroll
                for (int nb = 0; nb < 4; nb++) {
                    mma16816(acc[mi][2 * nb], ah[mi], &bh[nb][0]);
                    mma16816(acc[mi][2 * nb + 1], ah[mi], &bh[nb][2]);
                }
            // Al * Bh
            ldsm4(al[0], Al + aoff[0] + ko);
            ldsm4(al[1], Al + aoff[1] + ko);
#pragma unroll
            for (int mi = 0; mi < 2; mi++)
#pragma unroll
                for (int nb = 0; nb < 4; nb++) {
                    mma16816(acc[mi][2 * nb], al[mi], &bh[nb][0]);
                    mma16816(acc[mi][2 * nb + 1], al[mi], &bh[nb][2]);
                }
            // Ah * Bl
#pragma unroll
            for (int nb = 0; nb < 4; nb++) ldsm4(bl[nb], Bl + boff[nb] + ko);
#pragma unroll
            for (int mi = 0; mi < 2; mi++)
#pragma unroll
                for (int nb = 0; nb < 4; nb++) {
                    mma16816(acc[mi][2 * nb], ah[mi], &bl[nb][0]);
                    mma16816(acc[mi][2 * nb + 1], ah[mi], &bl[nb][2]);
                }
        }
    }

    // Store accumulators
    int mrow0 = rowBase + wm * 32;
    int col0 = nBase + wn * 64 + (lane & 3) * 2;
#pragma unroll
    for (int mi = 0; mi < 2; mi++)
#pragma unroll
        for (int h = 0; h < 2; h++) {
            int row = mrow0 + mi * 16 + (lane >> 2) + h * 8;
            if (row < M) {
                float* yp = Y + (size_t)row * XW + col0;
#pragma unroll
                for (int ni = 0; ni < 8; ni++)
                    *reinterpret_cast<float2*>(yp + ni * 8) =
                        make_float2(acc[mi][ni][2 * h], acc[mi][ni][2 * h + 1]);
            }
        }
}

// ===========================================================================
// fp32 epilogue: out = sum_j relu(Y[:,jblk] @ W[i,j] + b[i,j])
// ===========================================================================
__global__ __launch_bounds__(256) void k_epi(const float* __restrict__ Y,
                                             const float* __restrict__ Wall,
                                             const float* __restrict__ ball,
                                             float* __restrict__ out,
                                             int M, int ilev) {
    __shared__ float As[16][132];
    __shared__ float Bs[16][128];
    int tid = threadIdx.x;
    int tx = tid & 15;
    int ty = tid >> 4;
    int rowBase = blockIdx.x * 128;

    float sum[8][8];
#pragma unroll
    for (int i = 0; i < 8; i++)
#pragma unroll
        for (int j = 0; j < 8; j++) sum[i][j] = 0.f;

    for (int jb = 0; jb < 3; jb++) {
        const float* W = Wall + (size_t)(ilev * 3 + jb) * DIM * DIM;
        float acc[8][8];
#pragma unroll
        for (int i = 0; i < 8; i++)
#pragma unroll
            for (int j = 0; j < 8; j++) acc[i][j] = 0.f;

        for (int k0 = 0; k0 < DIM; k0 += 16) {
#pragma unroll
            for (int l = 0; l < 2; l++) {
                int s = tid + l * 256;
                int r = s >> 2;
                int kq = (s & 3) * 4;
                int grow = rowBase + r;
                float4 v = make_float4(0.f, 0.f, 0.f, 0.f);
                if (grow < M)
                    v = *reinterpret_cast<const float4*>(Y + (size_t)grow * XW + jb * DIM + k0 + kq);
                As[kq + 0][r] = v.x;
                As[kq + 1][r] = v.y;
                As[kq + 2][r] = v.z;
                As[kq + 3][r] = v.w;
            }
#pragma unroll
            for (int l = 0; l < 2; l++) {
                int s = tid + l * 256;
                int kr = s >> 5;
                int c4 = (s & 31) * 4;
                *reinterpret_cast<float4*>(&Bs[kr][c4]) =
                    *reinterpret_cast<const float4*>(W + (size_t)(k0 + kr) * DIM + c4);
            }
            __syncthreads();
#pragma unroll
            for (int kk = 0; kk < 16; kk++) {
                float a[8], b[8];
                *reinterpret_cast<float4*>(a) = *reinterpret_cast<const float4*>(&As[kk][ty * 8]);
                *reinterpret_cast<float4*>(a + 4) = *reinterpret_cast<const float4*>(&As[kk][ty * 8 + 4]);
                *reinterpret_cast<float4*>(b) = *reinterpret_cast<const float4*>(&Bs[kk][tx * 8]);
                *reinterpret_cast<float4*>(b + 4) = *reinterpret_cast<const float4*>(&Bs[kk][tx * 8 + 4]);
#pragma unroll
                for (int i = 0; i < 8; i++)
#pragma unroll
                    for (int j = 0; j < 8; j++) acc[i][j] += a[i] * b[j];
            }
            __syncthreads();
        }
        const float* bvec = ball + (size_t)(ilev * 3 + jb) * DIM;
#pragma unroll
        for (int j = 0; j < 8; j++) {
            float bb = bvec[tx * 8 + j];
#pragma unroll
            for (int i = 0; i < 8; i++) sum[i][j] += fmaxf(acc[i][j] + bb, 0.f);
        }
    }

#pragma unroll
    for (int i = 0; i < 8; i++) {
        int grow = rowBase + ty * 8 + i;
        if (grow < M) {
            float* op = out + (size_t)grow * DIM + tx * 8;
            *reinterpret_cast<float4*>(op) = make_float4(sum[i][0], sum[i][1], sum[i][2], sum[i][3]);
            *reinterpret_cast<float4*>(op + 4) = make_float4(sum[i][4], sum[i][5], sum[i][6], sum[i][7]);
        }
    }
}

// ===========================================================================
extern "C" void kernel_launch(void* const* d_in, const int* in_sizes, int n_in,
                              void* d_out, int out_size) {
    const float* adj0 = (const float*)d_in[0];
    const float* adj1 = (const float*)d_in[1];
    const float* adj2 = (const float*)d_in[2];
    const float* h0 = (const float*)d_in[3];
    const float* h1 = (const float*)d_in[4];
    const float* h2 = (const float*)d_in[5];
    const int* idx0 = (const int*)d_in[6];
    const int* idx1 = (const int*)d_in[7];
    const float* Ws = (const float*)d_in[8];
    const float* bs = (const float*)d_in[9];
    float* out = (float*)d_out;

    float *X0, *X1, *X2, *Y0, *Y1, *Y2;
    cudaGetSymbolAddress((void**)&X0, g_X0);
    cudaGetSymbolAddress((void**)&X1, g_X1);
    cudaGetSymbolAddress((void**)&X2, g_X2);
    cudaGetSymbolAddress((void**)&Y0, g_Y0);
    cudaGetSymbolAddress((void**)&Y1, g_Y1);
    cudaGetSymbolAddress((void**)&Y2, g_Y2);

    cudaFuncSetAttribute(k_mma, cudaFuncAttributeMaxDynamicSharedMemorySize, SMEM_TOTAL);

    // 1. Zero scatter-target feature rows of Xt
    k_zero<<<512, 256>>>(X0 + (size_t)128 * N0, 256 * N0 / 4);
    k_zero<<<256, 256>>>(X1 + (size_t)256 * N1, 128 * N1 / 4);

    // 2. Build Xt (transposed feature blocks)
    // Level 0:
    k_trans<<<(N0 + 31) / 32, 256>>>(X0, N0, h0, N0, nullptr, nullptr, 0);
    k_scatter<<<N1, 128>>>(X0, N0, h1, idx0, nullptr, 128);
    k_scatter<<<N2, 128>>>(X0, N0, h2, idx0, idx1, 256);
    // Level 1:
    k_trans<<<(N1 + 31) / 32, 256>>>(X1, N1, h0, N1, idx0, nullptr, 0);
    k_trans<<<(N1 + 31) / 32, 256>>>(X1, N1, h1, N1, nullptr, nullptr, 128);
    k_scatter<<<N2, 128>>>(X1, N1, h2, idx1, nullptr, 256);
    // Level 2:
    k_trans<<<(N2 + 31) / 32, 256>>>(X2, N2, h0, N2, idx0, idx1, 0);
    k_trans<<<(N2 + 31) / 32, 256>>>(X2, N2, h1, N2, idx1, nullptr, 128);
    k_trans<<<(N2 + 31) / 32, 256>>>(X2, N2, h2, N2, nullptr, nullptr, 256);

    // 3. Y_i = adj_i @ X_i via bf16-split tensor cores
    k_mma<<<333, 256, SMEM_TOTAL>>>(adj0, adj1, adj2, X0, X1, X2, Y0, Y1, Y2);

    // 4. Epilogue
    k_epi<<<(N0 + 127) / 128, 256>>>(Y0, Ws, bs, out, N0, 0);
    k_epi<<<(N1 + 127) / 128, 256>>>(Y1, Ws, bs, out + (size_t)N0 * DIM, N1, 1);
    k_epi<<<(N2 + 127) / 128, 256>>>(Y2, Ws, bs, out + (size_t)(N0 + N1) * DIM, N2, 2);
}

// round 6
// speedup vs baseline: 3.6670x; 1.1896x over previous
#include <cuda_runtime.h>
#include <cuda_bf16.h>
#include <cstdint>

#define N0 8000
#define N1 4000
#define N2 2000
#define DIM 128
#define XW 384

// bf16 hi/lo planes for adj (prepass-converted)
__device__ __nv_bfloat16 g_Ah0[(size_t)N0 * N0];
__device__ __nv_bfloat16 g_Al0[(size_t)N0 * N0];
__device__ __nv_bfloat16 g_Ah1[(size_t)N1 * N1];
__device__ __nv_bfloat16 g_Al1[(size_t)N1 * N1];
__device__ __nv_bfloat16 g_Ah2[(size_t)N2 * N2];
__device__ __nv_bfloat16 g_Al2[(size_t)N2 * N2];
// Xt = X^T [384][N_i], bf16 hi/lo
__device__ __nv_bfloat16 g_Bh0[XW * N0];
__device__ __nv_bfloat16 g_Bl0[XW * N0];
__device__ __nv_bfloat16 g_Bh1[XW * N1];
__device__ __nv_bfloat16 g_Bl1[XW * N1];
__device__ __nv_bfloat16 g_Bh2[XW * N2];
__device__ __nv_bfloat16 g_Bl2[XW * N2];
// fp32 Y = adj @ X
__device__ float g_Y0[N0 * XW];
__device__ float g_Y1[N1 * XW];
__device__ float g_Y2[N2 * XW];

// ===========================================================================
// helpers
// ===========================================================================
__device__ __forceinline__ uint32_t smem_to_u32(const void* p) {
    uint32_t a;
    asm("{ .reg .u64 t; cvta.to.shared.u64 t, %1; cvt.u32.u64 %0, t; }" : "=r"(a) : "l"(p));
    return a;
}
__device__ __forceinline__ void ldsm4(uint32_t* r, uint32_t addr) {
    asm volatile("ldmatrix.sync.aligned.m8n8.x4.shared.b16 {%0,%1,%2,%3}, [%4];"
                 : "=r"(r[0]), "=r"(r[1]), "=r"(r[2]), "=r"(r[3]) : "r"(addr));
}
__device__ __forceinline__ void mma16816(float* c, const uint32_t* a, const uint32_t* b) {
    asm volatile(
        "mma.sync.aligned.m16n8k16.row.col.f32.bf16.bf16.f32 "
        "{%0,%1,%2,%3}, {%4,%5,%6,%7}, {%8,%9}, {%0,%1,%2,%3};"
        : "+f"(c[0]), "+f"(c[1]), "+f"(c[2]), "+f"(c[3])
        : "r"(a[0]), "r"(a[1]), "r"(a[2]), "r"(a[3]), "r"(b[0]), "r"(b[1]));
}
__device__ __forceinline__ void cpa16(uint32_t d, const void* s, int sz) {
    asm volatile("cp.async.cg.shared.global [%0], [%1], 16, %2;"
                 :: "r"(d), "l"(s), "r"(sz) : "memory");
}
#define CP_COMMIT() asm volatile("cp.async.commit_group;" ::: "memory")
#define CP_WAIT2() asm volatile("cp.async.wait_group 2;" ::: "memory")

__device__ __forceinline__ uint32_t pkbits(__nv_bfloat16 x, __nv_bfloat16 y) {
    __nv_bfloat162 t;
    t.x = x; t.y = y;
    return reinterpret_cast<uint32_t&>(t);
}
__device__ __forceinline__ void split2(float a, float b, uint32_t& hi, uint32_t& lo) {
    __nv_bfloat16 xa = __float2bfloat16_rn(a), xb = __float2bfloat16_rn(b);
    hi = pkbits(xa, xb);
    lo = pkbits(__float2bfloat16_rn(a - __bfloat162float(xa)),
                __float2bfloat16_rn(b - __bfloat162float(xb)));
}

// ===========================================================================
// Prepass: fp32 -> bf16 hi/lo planes
// ===========================================================================
__global__ void k_cvt(const float4* __restrict__ in, uint2* __restrict__ hi,
                      uint2* __restrict__ lo, int n4) {
    int i = blockIdx.x * blockDim.x + threadIdx.x;
    int stride = gridDim.x * blockDim.x;
    for (; i < n4; i += stride) {
        float4 v = in[i];
        uint2 h, l;
        split2(v.x, v.y, h.x, l.x);
        split2(v.z, v.w, h.y, l.y);
        hi[i] = h;
        lo[i] = l;
    }
}

__global__ void k_zero(float* __restrict__ p, int n4) {
    int i = blockIdx.x * blockDim.x + threadIdx.x;
    int stride = gridDim.x * blockDim.x;
    float4 z = make_float4(0.f, 0.f, 0.f, 0.f);
    for (; i < n4; i += stride) reinterpret_cast<float4*>(p)[i] = z;
}

// Transposed placement into bf16 hi/lo Xt: Xt[rowOff+f][r] = H[chain(r)][f]
__global__ __launch_bounds__(256) void k_trans(__nv_bfloat16* __restrict__ Bh,
                                               __nv_bfloat16* __restrict__ Bl, int ld,
                                               const float* __restrict__ H, int rows,
                                               const int* __restrict__ s1,
                                               const int* __restrict__ s2, int rowOff) {
    __shared__ float tile[128][33];
    int tid = threadIdx.x;
    int r0 = blockIdx.x * 32;
#pragma unroll
    for (int t = 0; t < 4; t++) {
        int g = tid + t * 256;
        int r = g >> 5;
        int c4 = g & 31;
        int sr = r0 + r;
        float4 v = make_float4(0.f, 0.f, 0.f, 0.f);
        if (sr < rows) {
            int s = sr;
            if (s2) s = s2[s];
            if (s1) s = s1[s];
            v = *reinterpret_cast<const float4*>(H + (size_t)s * DIM + c4 * 4);
        }
        tile[c4 * 4 + 0][r] = v.x;
        tile[c4 * 4 + 1][r] = v.y;
        tile[c4 * 4 + 2][r] = v.z;
        tile[c4 * 4 + 3][r] = v.w;
    }
    __syncthreads();
    int f = tid >> 1;
    int half = tid & 1;
#pragma unroll
    for (int m4 = 0; m4 < 4; m4++) {
        int lc = half * 16 + m4 * 4;
        int col = r0 + lc;
        if (col < rows) {
            uint2 h, l;
            split2(tile[f][lc], tile[f][lc + 1], h.x, l.x);
            split2(tile[f][lc + 2], tile[f][lc + 3], h.y, l.y);
            size_t off = (size_t)(rowOff + f) * ld + col;
            *reinterpret_cast<uint2*>(Bh + off) = h;
            *reinterpret_cast<uint2*>(Bl + off) = l;
        }
    }
}

// Scattered placement (up path), bf16 hi/lo outputs
__global__ void k_scatter(__nv_bfloat16* __restrict__ Bh, __nv_bfloat16* __restrict__ Bl,
                          int ld, const float* __restrict__ H,
                          const int* __restrict__ d1, const int* __restrict__ d2, int rowOff) {
    int r = blockIdx.x;
    int f = threadIdx.x;
    float v = H[(size_t)r * DIM + f];
    int dr = r;
    if (d2) dr = d2[dr];
    if (d1) dr = d1[dr];
    __nv_bfloat16 h = __float2bfloat16_rn(v);
    size_t off = (size_t)(rowOff + f) * ld + dr;
    Bh[off] = h;
    Bl[off] = __float2bfloat16_rn(v - __bfloat162float(h));
}

// ===========================================================================
// bf16-split mma.sync GEMM with cp.async pipeline.
// CTA tile: M=64, N=128. 4 stages x 24KB. Grid: 660 CTAs (longest level first).
// ===========================================================================
#define STAGE_BYTES 24576
#define OFF_AH 0
#define OFF_AL 4096
#define OFF_BH 8192
#define OFF_BL 16384
#define SMEM_MMA (4 * STAGE_BYTES)   // 98304

__device__ __forceinline__ void issue_stage(
    uint32_t stg, const __nv_bfloat16* Ah, const __nv_bfloat16* Al,
    const __nv_bfloat16* Bh, const __nv_bfloat16* Bl,
    int rowBase, int nBase, int M, int K, int k0, int tid) {
    // A hi/lo: 64 rows x 4 chunks of 16B
    {
        int row = tid >> 2, c = tid & 3;
        int gk = k0 + c * 8;
        size_t so = (size_t)(rowBase + row) * K + gk;
        uint32_t d = stg + row * 64 + (((c) ^ ((row >> 1) & 3)) << 4);
        int p = (rowBase + row < M && gk < K) ? 16 : 0;
        cpa16(d + OFF_AH, Ah + so, p);
        cpa16(d + OFF_AL, Al + so, p);
    }
    // B hi/lo: 128 rows x 4 chunks
#pragma unroll
    for (int i = 0; i < 2; i++) {
        int t = tid + i * 256;
        int row = t >> 2, c = t & 3;
        int gk = k0 + c * 8;
        size_t so = (size_t)(nBase + row) * K + gk;
        uint32_t d = stg + row * 64 + (((c) ^ ((row >> 1) & 3)) << 4);
        int p = (gk < K) ? 16 : 0;
        cpa16(d + OFF_BH, Bh + so, p);
        cpa16(d + OFF_BL, Bl + so, p);
    }
}

__global__ __launch_bounds__(256, 2)
void k_mma(const __nv_bfloat16* __restrict__ Ah0, const __nv_bfloat16* __restrict__ Al0,
           const __nv_bfloat16* __restrict__ Ah1, const __nv_bfloat16* __restrict__ Al1,
           const __nv_bfloat16* __restrict__ Ah2, const __nv_bfloat16* __restrict__ Al2,
           const __nv_bfloat16* __restrict__ Bh0, const __nv_bfloat16* __restrict__ Bl0,
           const __nv_bfloat16* __restrict__ Bh1, const __nv_bfloat16* __restrict__ Bl1,
           const __nv_bfloat16* __restrict__ Bh2, const __nv_bfloat16* __restrict__ Bl2,
           float* __restrict__ Y0, float* __restrict__ Y1, float* __restrict__ Y2) {
    extern __shared__ char sm[];
    int tid = threadIdx.x;
    int lane = tid & 31;
    int wid = tid >> 5;
    int bx = blockIdx.x;

    const __nv_bfloat16 *Ah, *Al, *Bh, *Bl;
    float* Y;
    int M, mt, nt;
    if (bx < 375) {
        Ah = Ah0; Al = Al0; Bh = Bh0; Bl = Bl0; Y = Y0; M = N0; mt = bx / 3; nt = bx % 3;
    } else if (bx < 564) {
        int t = bx - 375;
        Ah = Ah1; Al = Al1; Bh = Bh1; Bl = Bl1; Y = Y1; M = N1; mt = t / 3; nt = t % 3;
    } else {
        int t = bx - 564;
        Ah = Ah2; Al = Al2; Bh = Bh2; Bl = Bl2; Y = Y2; M = N2; mt = t / 3; nt = t % 3;
    }
    int K = M;
    int rowBase = mt * 64;
    int nBase = nt * 128;
    int nIter = (K + 31) / 32;

    uint32_t sbase = smem_to_u32(sm);
    int wm = wid & 1;   // 2 m-warps x 32 rows
    int wn = wid >> 1;  // 4 n-warps x 32 cols

    // ldmatrix lane geometry
    int rA = lane & 15;
    int cA = lane >> 4;                          // chunk add for A
    int rBl = (lane & 7) + ((lane >> 4) & 1) * 8;
    int cB = (lane >> 3) & 1;                    // chunk add for B
    uint32_t arow[2], aswz[2], brow[2], bswz[2];
#pragma unroll
    for (int mi = 0; mi < 2; mi++) {
        int r = wm * 32 + mi * 16 + rA;
        arow[mi] = (uint32_t)r * 64;
        aswz[mi] = (r >> 1) & 3;
    }
#pragma unroll
    for (int nb = 0; nb < 2; nb++) {
        int r = wn * 32 + nb * 16 + rBl;
        brow[nb] = (uint32_t)r * 64;
        bswz[nb] = (r >> 1) & 3;
    }

    float acc[2][4][4];
#pragma unroll
    for (int mi = 0; mi < 2; mi++)
#pragma unroll
        for (int ni = 0; ni < 4; ni++)
#pragma unroll
            for (int c = 0; c < 4; c++) acc[mi][ni][c] = 0.f;

    // prologue: stages 0..2
#pragma unroll
    for (int s = 0; s < 3; s++) {
        issue_stage(sbase + s * STAGE_BYTES, Ah, Al, Bh, Bl, rowBase, nBase, M, K, s * 32, tid);
        CP_COMMIT();
    }

    for (int it = 0; it < nIter; it++) {
        CP_WAIT2();
        __syncthreads();
        if (it + 3 < nIter)
            issue_stage(sbase + ((it + 3) & 3) * STAGE_BYTES, Ah, Al, Bh, Bl,
                        rowBase, nBase, M, K, (it + 3) * 32, tid);
        CP_COMMIT();

        uint32_t stg = sbase + (it & 3) * STAGE_BYTES;
#pragma unroll
        for (int k16 = 0; k16 < 2; k16++) {
            uint32_t ah[2][4], al[2][4], bh[2][4], bl[2][4];
#pragma unroll
            for (int mi = 0; mi < 2; mi++) {
                uint32_t off = arow[mi] + ((((uint32_t)(k16 * 2 + cA)) ^ aswz[mi]) << 4);
                ldsm4(ah[mi], stg + OFF_AH + off);
                ldsm4(al[mi], stg + OFF_AL + off);
            }
#pragma unroll
            for (int nb = 0; nb < 2; nb++) {
                uint32_t off = brow[nb] + ((((uint32_t)(k16 * 2 + cB)) ^ bswz[nb]) << 4);
                ldsm4(bh[nb], stg + OFF_BH + off);
                ldsm4(bl[nb], stg + OFF_BL + off);
            }
#pragma unroll
            for (int mi = 0; mi < 2; mi++)
#pragma unroll
                for (int nb = 0; nb < 2; nb++) {
                    mma16816(acc[mi][2 * nb], ah[mi], &bh[nb][0]);
                    mma16816(acc[mi][2 * nb + 1], ah[mi], &bh[nb][2]);
                    mma16816(acc[mi][2 * nb], al[mi], &bh[nb][0]);
                    mma16816(acc[mi][2 * nb + 1], al[mi], &bh[nb][2]);
                    mma16816(acc[mi][2 * nb], ah[mi], &bl[nb][0]);
                    mma16816(acc[mi][2 * nb + 1], ah[mi], &bl[nb][2]);
                }
        }
    }

    // store
    int colB = nBase + wn * 32 + (lane & 3) * 2;
#pragma unroll
    for (int mi = 0; mi < 2; mi++)
#pragma unroll
        for (int h = 0; h < 2; h++) {
            int row = rowBase + wm * 32 + mi * 16 + (lane >> 2) + h * 8;
            if (row < M) {
                float* yp = Y + (size_t)row * XW + colB;
#pragma unroll
                for (int ni = 0; ni < 4; ni++)
                    *reinterpret_cast<float2*>(yp + ni * 8) =
                        make_float2(acc[mi][ni][2 * h], acc[mi][ni][2 * h + 1]);
            }
        }
}

// ===========================================================================
// Fused fp32 epilogue: out_i = sum_j relu(Y_i[:,jblk] @ W[i,j] + b[i,j]), one launch
// ===========================================================================
__global__ __launch_bounds__(256) void k_epi(const float* __restrict__ Y0a,
                                             const float* __restrict__ Y1a,
                                             const float* __restrict__ Y2a,
                                             const float* __restrict__ Wall,
                                             const float* __restrict__ ball,
                                             float* __restrict__ outAll) {
    __shared__ float As[16][132];
    __shared__ float Bs[16][128];
    int tid = threadIdx.x;
    int tx = tid & 15;
    int ty = tid >> 4;
    int bx = blockIdx.x;

    const float* Y;
    float* out;
    int M, ilev, mt;
    if (bx < 63) {
        Y = Y0a; out = outAll; M = N0; ilev = 0; mt = bx;
    } else if (bx < 95) {
        Y = Y1a; out = outAll + (size_t)N0 * DIM; M = N1; ilev = 1; mt = bx - 63;
    } else {
        Y = Y2a; out = outAll + (size_t)(N0 + N1) * DIM; M = N2; ilev = 2; mt = bx - 95;
    }
    int rowBase = mt * 128;

    float sum[8][8];
#pragma unroll
    for (int i = 0; i < 8; i++)
#pragma unroll
        for (int j = 0; j < 8; j++) sum[i][j] = 0.f;

    for (int jb = 0; jb < 3; jb++) {
        const float* W = Wall + (size_t)(ilev * 3 + jb) * DIM * DIM;
        float acc[8][8];
#pragma unroll
        for (int i = 0; i < 8; i++)
#pragma unroll
            for (int j = 0; j < 8; j++) acc[i][j] = 0.f;

        for (int k0 = 0; k0 < DIM; k0 += 16) {
#pragma unroll
            for (int l = 0; l < 2; l++) {
                int s = tid + l * 256;
                int r = s >> 2;
                int kq = (s & 3) * 4;
                int grow = rowBase + r;
                float4 v = make_float4(0.f, 0.f, 0.f, 0.f);
                if (grow < M)
                    v = *reinterpret_cast<const float4*>(Y + (size_t)grow * XW + jb * DIM + k0 + kq);
                As[kq + 0][r] = v.x;
                As[kq + 1][r] = v.y;
                As[kq + 2][r] = v.z;
                As[kq + 3][r] = v.w;
            }
#pragma unroll
            for (int l = 0; l < 2; l++) {
                int s = tid + l * 256;
                int kr = s >> 5;
                int c4 = (s & 31) * 4;
                *reinterpret_cast<float4*>(&Bs[kr][c4]) =
                    *reinterpret_cast<const float4*>(W + (size_t)(k0 + kr) * DIM + c4);
            }
            __syncthreads();
#pragma unroll
            for (int kk = 0; kk < 16; kk++) {
                float a[8], b[8];
                *reinterpret_cast<float4*>(a) = *reinterpret_cast<const float4*>(&As[kk][ty * 8]);
                *reinterpret_cast<float4*>(a + 4) = *reinterpret_cast<const float4*>(&As[kk][ty * 8 + 4]);
                *reinterpret_cast<float4*>(b) = *reinterpret_cast<const float4*>(&Bs[kk][tx * 8]);
                *reinterpret_cast<float4*>(b + 4) = *reinterpret_cast<const float4*>(&Bs[kk][tx * 8 + 4]);
#pragma unroll
                for (int i = 0; i < 8; i++)
#pragma unroll
                    for (int j = 0; j < 8; j++) acc[i][j] += a[i] * b[j];
            }
            __syncthreads();
        }
        const float* bvec = ball + (size_t)(ilev * 3 + jb) * DIM;
#pragma unroll
        for (int j = 0; j < 8; j++) {
            float bb = bvec[tx * 8 + j];
#pragma unroll
            for (int i = 0; i < 8; i++) sum[i][j] += fmaxf(acc[i][j] + bb, 0.f);
        }
    }

#pragma unroll
    for (int i = 0; i < 8; i++) {
        int grow = rowBase + ty * 8 + i;
        if (grow < M) {
            float* op = out + (size_t)grow * DIM + tx * 8;
            *reinterpret_cast<float4*>(op) = make_float4(sum[i][0], sum[i][1], sum[i][2], sum[i][3]);
            *reinterpret_cast<float4*>(op + 4) = make_float4(sum[i][4], sum[i][5], sum[i][6], sum[i][7]);
        }
    }
}

// ===========================================================================
extern "C" void kernel_launch(void* const* d_in, const int* in_sizes, int n_in,
                              void* d_out, int out_size) {
    const float* adj0 = (const float*)d_in[0];
    const float* adj1 = (const float*)d_in[1];
    const float* adj2 = (const float*)d_in[2];
    const float* h0 = (const float*)d_in[3];
    const float* h1 = (const float*)d_in[4];
    const float* h2 = (const float*)d_in[5];
    const int* idx0 = (const int*)d_in[6];
    const int* idx1 = (const int*)d_in[7];
    const float* Ws = (const float*)d_in[8];
    const float* bs = (const float*)d_in[9];
    float* out = (float*)d_out;

    __nv_bfloat16 *Ah0, *Al0, *Ah1, *Al1, *Ah2, *Al2;
    __nv_bfloat16 *Bh0, *Bl0, *Bh1, *Bl1, *Bh2, *Bl2;
    float *Y0, *Y1, *Y2;
    cudaGetSymbolAddress((void**)&Ah0, g_Ah0);
    cudaGetSymbolAddress((void**)&Al0, g_Al0);
    cudaGetSymbolAddress((void**)&Ah1, g_Ah1);
    cudaGetSymbolAddress((void**)&Al1, g_Al1);
    cudaGetSymbolAddress((void**)&Ah2, g_Ah2);
    cudaGetSymbolAddress((void**)&Al2, g_Al2);
    cudaGetSymbolAddress((void**)&Bh0, g_Bh0);
    cudaGetSymbolAddress((void**)&Bl0, g_Bl0);
    cudaGetSymbolAddress((void**)&Bh1, g_Bh1);
    cudaGetSymbolAddress((void**)&Bl1, g_Bl1);
    cudaGetSymbolAddress((void**)&Bh2, g_Bh2);
    cudaGetSymbolAddress((void**)&Bl2, g_Bl2);
    cudaGetSymbolAddress((void**)&Y0, g_Y0);
    cudaGetSymbolAddress((void**)&Y1, g_Y1);
    cudaGetSymbolAddress((void**)&Y2, g_Y2);

    cudaFuncSetAttribute(k_mma, cudaFuncAttributeMaxDynamicSharedMemorySize, SMEM_MMA);

    // 1. Convert adj -> bf16 hi/lo planes
    k_cvt<<<2048, 256>>>((const float4*)adj0, (uint2*)Ah0, (uint2*)Al0, (int)((size_t)N0 * N0 / 4));
    k_cvt<<<1024, 256>>>((const float4*)adj1, (uint2*)Ah1, (uint2*)Al1, N1 * N1 / 4);
    k_cvt<<<512, 256>>>((const float4*)adj2, (uint2*)Ah2, (uint2*)Al2, N2 * N2 / 4);

    // 2. Zero scatter-target regions of Xt (hi & lo)
    k_zero<<<256, 256>>>((float*)(Bh0 + (size_t)128 * N0), 256 * N0 * 2 / 16);
    k_zero<<<256, 256>>>((float*)(Bl0 + (size_t)128 * N0), 256 * N0 * 2 / 16);
    k_zero<<<128, 256>>>((float*)(Bh1 + (size_t)256 * N1), 128 * N1 * 2 / 16);
    k_zero<<<128, 256>>>((float*)(Bl1 + (size_t)256 * N1), 128 * N1 * 2 / 16);

    // 3. Build Xt (bf16 hi/lo)
    k_trans<<<(N0 + 31) / 32, 256>>>(Bh0, Bl0, N0, h0, N0, nullptr, nullptr, 0);
    k_scatter<<<N1, 128>>>(Bh0, Bl0, N0, h1, idx0, nullptr, 128);
    k_scatter<<<N2, 128>>>(Bh0, Bl0, N0, h2, idx0, idx1, 256);
    k_trans<<<(N1 + 31) / 32, 256>>>(Bh1, Bl1, N1, h0, N1, idx0, nullptr, 0);
    k_trans<<<(N1 + 31) / 32, 256>>>(Bh1, Bl1, N1, h1, N1, nullptr, nullptr, 128);
    k_scatter<<<N2, 128>>>(Bh1, Bl1, N1, h2, idx1, nullptr, 256);
    k_trans<<<(N2 + 31) / 32, 256>>>(Bh2, Bl2, N2, h0, N2, idx0, idx1, 0);
    k_trans<<<(N2 + 31) / 32, 256>>>(Bh2, Bl2, N2, h1, N2, idx1, nullptr, 128);
    k_trans<<<(N2 + 31) / 32, 256>>>(Bh2, Bl2, N2, h2, N2, nullptr, nullptr, 256);

    // 4. Y_i = adj_i @ X_i (tensor cores, cp.async pipeline, balanced M=64 tiles)
    k_mma<<<660, 256, SMEM_MMA>>>(Ah0, Al0, Ah1, Al1, Ah2, Al2,
                                  Bh0, Bl0, Bh1, Bl1, Bh2, Bl2, Y0, Y1, Y2);

    // 5. Fused epilogue
    k_epi<<<111, 256>>>(Y0, Y1, Y2, Ws, bs, out);
}